// round 4
// baseline (speedup 1.0000x reference)
#include <cuda_runtime.h>

typedef unsigned long long ull;

// ---- packed f32x2 helpers (sm_100+) ---------------------------------------
__device__ __forceinline__ ull f2pack(float lo, float hi) {
    ull r; asm("mov.b64 %0, {%1, %2};" : "=l"(r) : "f"(lo), "f"(hi)); return r;
}
__device__ __forceinline__ void f2unpack(ull v, float& lo, float& hi) {
    asm("mov.b64 {%0, %1}, %2;" : "=f"(lo), "=f"(hi) : "l"(v));
}
__device__ __forceinline__ ull ffma2(ull a, ull b, ull c) {
    ull d; asm("fma.rn.f32x2 %0, %1, %2, %3;" : "=l"(d) : "l"(a), "l"(b), "l"(c));
    return d;
}

// Scratch (device globals — no allocation allowed)
__device__ float g_qkv[1024 * 1536];   // [B*N][3C]
__device__ float g_att[1024 * 512];    // [B*N][C]

// ---------------------------------------------------------------------------
// GEMM: C[M][N] = A[M][K] @ B[N][K]^T (+ bias[N]), fp32 via packed FFMA2.
// Tile 64x64, BK=16, 128 threads, 4 rows x 8 cols per thread.
// A staged in smem DUPLICATED as (a,a) pairs so f32x2 operands need no packs.
// ---------------------------------------------------------------------------
template<bool HAS_BIAS>
__global__ __launch_bounds__(128) void gemm_kt2(
    const float* __restrict__ A, const float* __restrict__ B,
    const float* __restrict__ bias, float* __restrict__ C,
    int M, int N, int K)
{
    __shared__ __align__(16) float As2[16][128];  // duplicated A: [k][2m],[2m+1]
    __shared__ __align__(16) float Bs[16][64];

    int tid = threadIdx.x;
    int tx = tid & 7;     // 8 col-groups of 8
    int ty = tid >> 3;    // 16 row-groups of 4
    int row0 = blockIdx.y * 64;
    int col0 = blockIdx.x * 64;

    ull acc[4][4];
    #pragma unroll
    for (int i = 0; i < 4; i++)
        #pragma unroll
        for (int j = 0; j < 4; j++) acc[i][j] = 0ull;

    int lr = tid >> 1;          // 0..63
    int lk = (tid & 1) * 8;     // 0 or 8
    const float* Ap = A + (size_t)(row0 + lr) * K + lk;
    const float* Bp = B + (size_t)(col0 + lr) * K + lk;

    for (int k0 = 0; k0 < K; k0 += 16) {
        float4 a0 = *(const float4*)(Ap + k0);
        float4 a1 = *(const float4*)(Ap + k0 + 4);
        float4 b0 = *(const float4*)(Bp + k0);
        float4 b1 = *(const float4*)(Bp + k0 + 4);
        float av[8] = {a0.x, a0.y, a0.z, a0.w, a1.x, a1.y, a1.z, a1.w};
        float bv[8] = {b0.x, b0.y, b0.z, b0.w, b1.x, b1.y, b1.z, b1.w};
        #pragma unroll
        for (int i = 0; i < 8; i++) {
            *(float2*)&As2[lk + i][2 * lr] = make_float2(av[i], av[i]);
            Bs[lk + i][lr] = bv[i];
        }
        __syncthreads();

        #pragma unroll
        for (int k = 0; k < 16; k++) {
            ulonglong2 aA = *(const ulonglong2*)&As2[k][8 * ty];
            ulonglong2 aB = *(const ulonglong2*)&As2[k][8 * ty + 4];
            ulonglong2 bA = *(const ulonglong2*)&Bs[k][8 * tx];
            ulonglong2 bB = *(const ulonglong2*)&Bs[k][8 * tx + 4];
            ull ar[4] = {aA.x, aA.y, aB.x, aB.y};   // (r_i, r_i) pairs
            ull br[4] = {bA.x, bA.y, bB.x, bB.y};   // (c_2j, c_2j+1) pairs
            #pragma unroll
            for (int i = 0; i < 4; i++)
                #pragma unroll
                for (int j = 0; j < 4; j++)
                    acc[i][j] = ffma2(ar[i], br[j], acc[i][j]);
        }
        __syncthreads();
    }

    float bvv[8];
    #pragma unroll
    for (int j = 0; j < 8; j++)
        bvv[j] = HAS_BIAS ? bias[col0 + 8 * tx + j] : 0.f;

    #pragma unroll
    for (int i = 0; i < 4; i++) {
        float o[8];
        #pragma unroll
        for (int j = 0; j < 4; j++) f2unpack(acc[i][j], o[2 * j], o[2 * j + 1]);
        #pragma unroll
        for (int j = 0; j < 8; j++) o[j] += bvv[j];
        float* cp = &C[(size_t)(row0 + 4 * ty + i) * N + col0 + 8 * tx];
        *(float4*)cp       = make_float4(o[0], o[1], o[2], o[3]);
        *(float4*)(cp + 4) = make_float4(o[4], o[5], o[6], o[7]);
    }
}

// ---------------------------------------------------------------------------
// Fourier attention core.
// Grid: (4 q-tiles of 64, B*H=32). Block: 256 threads.
// Thread t: query q = t&63, key-subrange sub = t>>6 (64 keys each).
// score = R^64 * prod_{4 chunks of 16 dims} [prod sin(u) / prod u], u=R(q-k).
// No per-element guards: pd==0 (only possible via exact-zero u) triggers a
// rolled slow path. V accumulation uses packed FFMA2.
// ---------------------------------------------------------------------------
__global__ __launch_bounds__(256) void attn_kernel(
    const float* __restrict__ qkv, const float* __restrict__ paramR,
    float* __restrict__ outp)
{
    extern __shared__ float sm[];
    float* kS = sm;               // [256][64] : -R * k
    float* vS = sm + 256 * 64;    // [256][64] : v

    int tid = threadIdx.x;
    int bh = blockIdx.y;
    int b = bh >> 3;
    int h = bh & 7;
    int qbase = blockIdx.x * 64;
    float R = paramR[0];

    const float* base = qkv + (size_t)(b * 256) * 1536 + h * 64;

    for (int i = tid; i < 256 * 16; i += 256) {
        int n = i >> 4;
        int d4 = (i & 15) << 2;
        float4 kv = *(const float4*)(base + (size_t)n * 1536 + 512 + d4);
        float4 ks;
        ks.x = -R * kv.x; ks.y = -R * kv.y; ks.z = -R * kv.z; ks.w = -R * kv.w;
        *(float4*)&kS[n * 64 + d4] = ks;
        *(float4*)&vS[n * 64 + d4] = *(const float4*)(base + (size_t)n * 1536 + 1024 + d4);
    }

    int q = tid & 63;
    int sub = tid >> 6;

    const float* qp = base + (size_t)(qbase + q) * 1536;
    float qr[64];
    #pragma unroll
    for (int d = 0; d < 64; d += 4) {
        float4 t = *(const float4*)(qp + d);
        qr[d + 0] = R * t.x; qr[d + 1] = R * t.y;
        qr[d + 2] = R * t.z; qr[d + 3] = R * t.w;
    }
    float R64;
    { float p = R; p *= p; p *= p; p *= p; p *= p; p *= p; p *= p; R64 = p; }

    __syncthreads();

    ull acc2[32];
    #pragma unroll
    for (int j = 0; j < 32; j++) acc2[j] = 0ull;
    float sumA = 0.f;

    const int kstart = sub * 64;
    for (int kk = kstart; kk < kstart + 64; kk++) {
        const float* kp = &kS[kk * 64];
        const float4* kp4 = (const float4*)kp;
        float sc = R64;
        #pragma unroll
        for (int c = 0; c < 4; c++) {
            float pn = 1.f, pd = 1.f;
            #pragma unroll
            for (int j4 = 0; j4 < 4; j4++) {
                float4 kv = kp4[c * 4 + j4];
                int dd = c * 16 + j4 * 4;
                float u0 = qr[dd + 0] + kv.x;
                float u1 = qr[dd + 1] + kv.y;
                float u2 = qr[dd + 2] + kv.z;
                float u3 = qr[dd + 3] + kv.w;
                float s0 = __sinf(u0), s1 = __sinf(u1);
                float s2 = __sinf(u2), s3 = __sinf(u3);
                pn *= (s0 * s1) * (s2 * s3);
                pd *= (u0 * u1) * (u2 * u3);
            }
            float r;
            if (pd != 0.f) {
                r = __fdividef(pn, pd);
            } else {
                // Exact-zero diff on some dim (reference: factor -> R, i.e.
                // ratio contribution 1). Essentially never taken.
                r = 1.f;
                #pragma unroll 1
                for (int j = c * 16; j < c * 16 + 16; j++) {
                    float u = R * qp[j] + kp[j];
                    if (u != 0.f) r *= __fdividef(__sinf(u), u);
                }
            }
            sc *= r;
        }
        float a2 = sc * sc;
        float a4 = a2 * a2;
        sumA += a4;
        ull a42 = f2pack(a4, a4);
        const ulonglong2* vp = (const ulonglong2*)&vS[kk * 64];
        #pragma unroll
        for (int j = 0; j < 16; j++) {
            ulonglong2 vv = vp[j];
            acc2[2 * j]     = ffma2(a42, vv.x, acc2[2 * j]);
            acc2[2 * j + 1] = ffma2(a42, vv.y, acc2[2 * j + 1]);
        }
    }

    __syncthreads();   // done reading kS/vS — reuse smem for reduction

    float* red = sm;   // [256][65]
    {
        float* rp = red + (sub * 64 + q) * 65;
        #pragma unroll
        for (int j = 0; j < 32; j++) {
            float lo, hi;
            f2unpack(acc2[j], lo, hi);
            rp[2 * j] = lo; rp[2 * j + 1] = hi;
        }
        rp[64] = sumA;
    }
    __syncthreads();

    {
        int q2 = tid & 63;
        int part = tid >> 6;
        const float* r0 = red + q2 * 65;
        const float* r1 = red + (64 + q2) * 65;
        const float* r2 = red + (128 + q2) * 65;
        const float* r3 = red + (192 + q2) * 65;
        float stot = r0[64] + r1[64] + r2[64] + r3[64];
        float inv = __fdividef(1.0f, stot + 1e-6f);
        float* dst = outp + (size_t)(b * 256 + qbase + q2) * 512 + h * 64;
        #pragma unroll
        for (int d = part * 16; d < part * 16 + 16; d++) {
            dst[d] = (r0[d] + r1[d] + r2[d] + r3[d]) * inv;
        }
    }
}

// ---------------------------------------------------------------------------
extern "C" void kernel_launch(void* const* d_in, const int* in_sizes, int n_in,
                              void* d_out, int out_size)
{
    const float* x      = (const float*)d_in[0];   // (4,256,512)
    const float* w_qkv  = (const float*)d_in[1];   // (1536,512)
    const float* w_proj = (const float*)d_in[2];   // (512,512)
    const float* b_proj = (const float*)d_in[3];   // (512,)
    const float* paramR = (const float*)d_in[4];   // (1,)
    float* out = (float*)d_out;                    // (4,256,512)

    float *qkv, *att;
    cudaGetSymbolAddress((void**)&qkv, g_qkv);
    cudaGetSymbolAddress((void**)&att, g_att);

    cudaFuncSetAttribute(attn_kernel,
                         cudaFuncAttributeMaxDynamicSharedMemorySize, 131072);

    // 1) QKV projection: [1024][1536] = x[1024][512] @ w_qkv^T
    gemm_kt2<false><<<dim3(1536 / 64, 1024 / 64), 128>>>(
        x, w_qkv, nullptr, qkv, 1024, 1536, 512);

    // 2) Fourier attention
    attn_kernel<<<dim3(4, 32), 256, 131072>>>(qkv, paramR, att);

    // 3) Output projection + bias
    gemm_kt2<true><<<dim3(512 / 64, 1024 / 64), 128>>>(
        att, w_proj, b_proj, out, 1024, 512, 512);
}